// round 14
// baseline (speedup 1.0000x reference)
#include <cuda_runtime.h>
#include <cuda_fp16.h>
#include <cstdint>

#define Dm   1024
#define Hn   16
#define HD   64
#define Bb   4
#define Tt   2048
#define BH   (Bb*Hn)
#define Mtot (Bb*Tt)
#define NX4  (Mtot*Dm/4)
#define NW4  (Dm*Dm/4)

// Split-fp16 GEMM operands
__device__ __half g_Xh[(size_t)Mtot * Dm];
__device__ __half g_Xl[(size_t)Mtot * Dm];
__device__ __half g_Wh[(size_t)3 * Dm * Dm];
__device__ __half g_Wl[(size_t)3 * Dm * Dm];
// Projection outputs. Q pre-scaled by 8*log2(e). Q/K split fp16; V^T single fp16.
__device__ __half g_Qh[(size_t)BH * Tt * HD];
__device__ __half g_Ql[(size_t)BH * Tt * HD];
__device__ __half g_Kh[(size_t)BH * Tt * HD];
__device__ __half g_Kl[(size_t)BH * Tt * HD];
__device__ __half g_Vt[(size_t)BH * HD * Tt];

// ---------------------------------------------------------------------------
__device__ __forceinline__ uint32_t smem_u32(const void* p) {
    uint32_t a;
    asm("{ .reg .u64 t; cvta.to.shared.u64 t, %1; cvt.u32.u64 %0, t; }"
        : "=r"(a) : "l"(p));
    return a;
}
__device__ __forceinline__ void cpa16(uint32_t s, const void* g) {
    asm volatile("cp.async.cg.shared.global [%0], [%1], 16;" :: "r"(s), "l"(g));
}
#define CP_COMMIT() asm volatile("cp.async.commit_group;" ::: "memory")
#define CP_WAIT(n)  asm volatile("cp.async.wait_group %0;" :: "n"(n) : "memory")

__device__ __forceinline__ void ldsm_x4(uint32_t& r0, uint32_t& r1,
                                        uint32_t& r2, uint32_t& r3, uint32_t a) {
    asm volatile("ldmatrix.sync.aligned.m8n8.x4.shared.b16 {%0,%1,%2,%3}, [%4];"
                 : "=r"(r0), "=r"(r1), "=r"(r2), "=r"(r3) : "r"(a));
}
// fp16 x fp16 -> fp32 accumulate
__device__ __forceinline__ void mma_ff32(float* c, const uint32_t* a,
                                         uint32_t b0, uint32_t b1) {
    asm volatile(
        "mma.sync.aligned.m16n8k16.row.col.f32.f16.f16.f32 "
        "{%0,%1,%2,%3}, {%4,%5,%6,%7}, {%8,%9}, {%0,%1,%2,%3};"
        : "+f"(c[0]), "+f"(c[1]), "+f"(c[2]), "+f"(c[3])
        : "r"(a[0]), "r"(a[1]), "r"(a[2]), "r"(a[3]), "r"(b0), "r"(b1));
}
// fp16 x fp16 -> fp16 accumulate (correction terms)
__device__ __forceinline__ void mma_ff16(uint32_t* c, const uint32_t* a,
                                         uint32_t b0, uint32_t b1) {
    asm volatile(
        "mma.sync.aligned.m16n8k16.row.col.f16.f16.f16.f16 "
        "{%0,%1}, {%2,%3,%4,%5}, {%6,%7}, {%0,%1};"
        : "+r"(c[0]), "+r"(c[1])
        : "r"(a[0]), "r"(a[1]), "r"(a[2]), "r"(a[3]), "r"(b0), "r"(b1));
}
__device__ __forceinline__ uint32_t packh2(float lo, float hi) {
    __half2 h = __floats2half2_rn(lo, hi);
    return *reinterpret_cast<uint32_t*>(&h);
}
__device__ __forceinline__ float h2lo(uint32_t u) {
    return __half2float(__ushort_as_half((unsigned short)(u & 0xffffu)));
}
__device__ __forceinline__ float h2hi(uint32_t u) {
    return __half2float(__ushort_as_half((unsigned short)(u >> 16)));
}
// guaranteed MUFU path
__device__ __forceinline__ float ex2f(float x) {
    float y;
    asm("ex2.approx.f32 %0, %1;" : "=f"(y) : "f"(x));
    return y;
}

// ---------------------------------------------------------------------------
// Merged split: X, Wq, Wk, Wv -> (hi, lo) fp16. 2 float4 per thread.
// Wv's lo digit is never read by proj (V uses XhWh only) -> not written.
// ---------------------------------------------------------------------------
__global__ __launch_bounds__(256) void split_all(
    const float* __restrict__ x, const float* __restrict__ wq,
    const float* __restrict__ wk, const float* __restrict__ wv)
{
#pragma unroll
    for (int jj = 0; jj < 2; jj++) {
        int i = blockIdx.x * 512 + jj * 256 + threadIdx.x;
        const float4* src;
        ushort4 *hi, *lo;
        bool write_lo = true;
        if (i < NX4) {
            src = (const float4*)x + i;
            hi = (ushort4*)g_Xh + i;
            lo = (ushort4*)g_Xl + i;
        } else {
            int j = i - NX4;
            int w = j >> 18;                 // NW4 = 2^18
            int o = j & (NW4 - 1);
            const float* ws = (w == 0) ? wq : (w == 1) ? wk : wv;
            src = (const float4*)ws + o;
            hi = (ushort4*)(g_Wh + (size_t)w * Dm * Dm) + o;
            lo = (ushort4*)(g_Wl + (size_t)w * Dm * Dm) + o;
            write_lo = (w != 2);
        }
        float4 v = *src;
        float f[4] = {v.x, v.y, v.z, v.w};
        unsigned short h[4], l[4];
#pragma unroll
        for (int j = 0; j < 4; j++) {
            __half hb = __float2half_rn(f[j]);
            __half lb = __float2half_rn(f[j] - __half2float(hb));
            h[j] = __half_as_ushort(hb);
            l[j] = __half_as_ushort(lb);
        }
        *hi = make_ushort4(h[0], h[1], h[2], h[3]);
        if (write_lo) *lo = make_ushort4(l[0], l[1], l[2], l[3]);
    }
}

// ---------------------------------------------------------------------------
// Projection GEMM (HMMA split-fp16). 128x128 tile, BK=32, 2-stage cp.async,
// 2 CTAs/SM. Units: Q,K -> XhWh + XlWh + XhWl (3 each);  V -> XhWh only (1).
// ---------------------------------------------------------------------------
#define BKp      32
#define NSTp     (Dm / BKp)         // 32
#define PITCH_P  80
#define TILE_P   (128 * PITCH_P)    // 10240
#define STG_P    (4 * TILE_P)       // 40960
#define GEMM_SMEM (2 * STG_P)       // 81920

__global__ __launch_bounds__(256, 2) void proj_mma_kernel(
    const float* __restrict__ bq, const float* __restrict__ bk,
    const float* __restrict__ bv)
{
    extern __shared__ char smem[];
    const int tid  = threadIdx.x;
    const int z    = blockIdx.z;
    const int m0   = blockIdx.x * 128;
    const int n0   = blockIdx.y * 128;

    const uint4* Xh4 = (const uint4*)g_Xh;
    const uint4* Xl4 = (const uint4*)g_Xl;
    const uint4* Wh4 = (const uint4*)(g_Wh + (size_t)z * Dm * Dm);
    const uint4* Wl4 = (const uint4*)(g_Wl + (size_t)z * Dm * Dm);
    const float* bias = (z == 0) ? bq : (z == 1) ? bk : bv;
    __half* OutH = (z == 0) ? g_Qh : g_Kh;
    __half* OutL = (z == 0) ? g_Ql : g_Kl;

    const uint32_t sb = smem_u32(smem);
    const int warp = tid >> 5, lane = tid & 31;
    const int wm = warp >> 2;
    const int wn = warp & 3;
    const int a_row = wm * 64 + (lane & 7) + ((lane >> 3) & 1) * 8;
    const uint32_t a_kb = ((lane >> 4) & 1) * 16;
    const int b_row = wn * 32 + (lane & 7) + ((lane >> 4) & 1) * 8;
    const uint32_t b_kb = ((lane >> 3) & 1) * 16;

    float acc[4][4][4];
    uint32_t ch[4][4][2];
#pragma unroll
    for (int i = 0; i < 4; i++)
#pragma unroll
        for (int j = 0; j < 4; j++) {
#pragma unroll
            for (int k = 0; k < 4; k++) acc[i][j][k] = 0.f;
            ch[i][j][0] = 0u; ch[i][j][1] = 0u;
        }

    auto issue_stage = [&](int s) {
        const uint32_t base = sb + (s & 1) * STG_P;
        const int kseg0 = s * (BKp / 8);
#pragma unroll
        for (int j = 0; j < 2; j++) {
            int idx = tid + 256 * j;
            int row = idx >> 2, seg = idx & 3;
            uint32_t so = (uint32_t)(row * PITCH_P + seg * 16);
            size_t ga = (size_t)(m0 + row) * 128 + kseg0 + seg;
            size_t gb = (size_t)(n0 + row) * 128 + kseg0 + seg;
            cpa16(base + so,              Xh4 + ga);
            cpa16(base + 2 * TILE_P + so, Wh4 + gb);
            if (z != 2) {
                cpa16(base + TILE_P + so,     Xl4 + ga);
                cpa16(base + 3 * TILE_P + so, Wl4 + gb);
            }
        }
        CP_COMMIT();
    };

    issue_stage(0);

    for (int s = 0; s < NSTp; s++) {
        if (s + 1 < NSTp) { issue_stage(s + 1); CP_WAIT(1); }
        else              { CP_WAIT(0); }
        __syncthreads();

        const uint32_t base = sb + (s & 1) * STG_P;
        const uint32_t Ah = base, Al = base + TILE_P;
        const uint32_t Bh = base + 2 * TILE_P, Bl = base + 3 * TILE_P;

#pragma unroll
        for (int ks = 0; ks < 2; ks++) {
            const uint32_t ko = ks * 32;
            uint32_t af[4][4], tf[4][4], bf[2][4];
#pragma unroll
            for (int ma = 0; ma < 4; ma++) {
                uint32_t ao = (uint32_t)((a_row + ma * 16) * PITCH_P) + ko + a_kb;
                ldsm_x4(af[ma][0], af[ma][1], af[ma][2], af[ma][3], Ah + ao);
            }
#pragma unroll
            for (int pb = 0; pb < 2; pb++) {
                uint32_t bo = (uint32_t)((b_row + pb * 16) * PITCH_P) + ko + b_kb;
                ldsm_x4(bf[pb][0], bf[pb][1], bf[pb][2], bf[pb][3], Bh + bo);
            }
            // main: Xh * Wh -> fp32 acc
#pragma unroll
            for (int ma = 0; ma < 4; ma++)
#pragma unroll
                for (int na = 0; na < 4; na++)
                    mma_ff32(acc[ma][na], af[ma],
                             bf[na >> 1][(na & 1) * 2], bf[na >> 1][(na & 1) * 2 + 1]);
            if (z != 2) {
                // corr: Xl * Wh -> fp16 acc
#pragma unroll
                for (int ma = 0; ma < 4; ma++) {
                    uint32_t ao = (uint32_t)((a_row + ma * 16) * PITCH_P) + ko + a_kb;
                    ldsm_x4(tf[ma][0], tf[ma][1], tf[ma][2], tf[ma][3], Al + ao);
                }
#pragma unroll
                for (int ma = 0; ma < 4; ma++)
#pragma unroll
                    for (int na = 0; na < 4; na++)
                        mma_ff16(ch[ma][na], tf[ma],
                                 bf[na >> 1][(na & 1) * 2], bf[na >> 1][(na & 1) * 2 + 1]);
                // corr: Xh * Wl -> fp16 acc
#pragma unroll
                for (int pb = 0; pb < 2; pb++) {
                    uint32_t bo = (uint32_t)((b_row + pb * 16) * PITCH_P) + ko + b_kb;
                    ldsm_x4(bf[pb][0], bf[pb][1], bf[pb][2], bf[pb][3], Bl + bo);
                }
#pragma unroll
                for (int ma = 0; ma < 4; ma++)
#pragma unroll
                    for (int na = 0; na < 4; na++)
                        mma_ff16(ch[ma][na], af[ma],
                                 bf[na >> 1][(na & 1) * 2], bf[na >> 1][(na & 1) * 2 + 1]);
            }
        }
        __syncthreads();
    }

    // epilogue: merge corrections, +bias, (Q: x 8*log2e), store
    const int gid = lane >> 2, tig = lane & 3;
    const float qscale = (z == 0) ? 11.541560327111707f : 1.0f;   // 8*log2(e)
#pragma unroll
    for (int ma = 0; ma < 4; ma++) {
#pragma unroll
        for (int na = 0; na < 4; na++) {
            const int col = n0 + wn * 32 + na * 8 + tig * 2;
            const float2 bv2 = *(const float2*)&bias[col];
            const int hh = col >> 6, d = col & 63;
            float c4[4];
            c4[0] = acc[ma][na][0] + h2lo(ch[ma][na][0]);
            c4[1] = acc[ma][na][1] + h2hi(ch[ma][na][0]);
            c4[2] = acc[ma][na][2] + h2lo(ch[ma][na][1]);
            c4[3] = acc[ma][na][3] + h2hi(ch[ma][na][1]);
#pragma unroll
            for (int half = 0; half < 2; half++) {
                const int row = m0 + wm * 64 + ma * 16 + gid + half * 8;
                const int t = row & 2047;
                const int bhidx = ((row >> 11) << 4) + hh;
                float v0 = (c4[half * 2 + 0] + bv2.x) * qscale;
                float v1 = (c4[half * 2 + 1] + bv2.y) * qscale;
                __half h0 = __float2half_rn(v0);
                __half h1 = __float2half_rn(v1);
                if (z < 2) {
                    __half l0 = __float2half_rn(v0 - __half2float(h0));
                    __half l1 = __float2half_rn(v1 - __half2float(h1));
                    size_t ix = ((size_t)bhidx * Tt + t) * HD + d;
                    uint32_t ph = ((uint32_t)__half_as_ushort(h1) << 16) |
                                   __half_as_ushort(h0);
                    uint32_t pl = ((uint32_t)__half_as_ushort(l1) << 16) |
                                   __half_as_ushort(l0);
                    *(uint32_t*)&OutH[ix] = ph;
                    *(uint32_t*)&OutL[ix] = pl;
                } else {
                    size_t ix = ((size_t)bhidx * HD + d) * Tt + t;
                    g_Vt[ix]      = h0;
                    g_Vt[ix + Tt] = h1;
                }
            }
        }
    }
}

// ---------------------------------------------------------------------------
// Flash attention, HMMA fp16, base-2 softmax (Q pre-scaled 8*log2e).
// S: QhKh (fp32 acc) + QlKh + QhKl (fp16 acc). PV: single product, P & V fp16.
// BQ=128 (8 warps x M16), BKV=64, 2-stage cp.async ring, 2 CTAs/SM.
// Causal skips: (a) fully-masked half of last tile (warps 0-3); (b) per-warp
// fully-masked MMA blocks on the diagonal tile (identity: those P rows are 0).
// ---------------------------------------------------------------------------
#define PITCHQ  144
#define AQ_B    (128 * PITCHQ)        // 18432 per Q array
#define KT_B    (64 * PITCHQ)         // 9216 per K array (64 t-rows x 64 d)
#define VT_B    (64 * PITCHQ)         // 9216 V^T (64 d-rows x 64 t)
#define ASTG_B  (2 * KT_B + VT_B)     // 27648
#define ATTN_SMEM (2 * AQ_B + 2 * ASTG_B)   // 92160

__global__ __launch_bounds__(256, 2) void attn_mma_kernel(float* __restrict__ out)
{
    extern __shared__ char smem[];
    const int tid  = threadIdx.x;
    const int w    = tid >> 5, lane = tid & 31;
    const int qi   = (int)gridDim.x - 1 - (int)blockIdx.x;   // long CTAs first
    const int bh   = blockIdx.y;
    const int q0   = qi * 128;
    const int n_kv = 2 * (qi + 1);

    const uint32_t sb  = smem_u32(smem);
    const uint32_t sQh = sb, sQl = sb + AQ_B;
    const uint32_t sT0 = sb + 2 * AQ_B;

    const int gid = lane >> 2, tig = lane & 3;
    const int arow = (lane & 7) + ((lane >> 3) & 1) * 8;
    const uint32_t akb = ((lane >> 4) & 1) * 16;
    const int brow = (lane & 7) + ((lane >> 4) & 1) * 8;
    const uint32_t bkb = ((lane >> 3) & 1) * 16;
    const int wmax = q0 + w * 16 + 15;     // warp's max q row

    // Q: 128 rows x 64 fp16 (hi+lo) — joins commit group 0
#pragma unroll
    for (int j = 0; j < 4; j++) {
        int idx = tid + 256 * j;
        int row = idx >> 3, seg = idx & 7;
        uint32_t so = (uint32_t)(row * PITCHQ + seg * 16);
        size_t g = ((size_t)bh * Tt + q0 + row) * HD + seg * 8;
        cpa16(sQh + so, g_Qh + g);
        cpa16(sQl + so, g_Ql + g);
    }
    auto loadKV = [&](int kt) {
        const uint32_t base = sT0 + (kt & 1) * ASTG_B;
        const int k0 = kt * 64;
#pragma unroll
        for (int j = 0; j < 2; j++) {
            int idx = tid + 256 * j;
            int row = idx >> 3, seg = idx & 7;
            uint32_t so = (uint32_t)(row * PITCHQ + seg * 16);
            size_t gk = ((size_t)bh * Tt + k0 + row) * HD + seg * 8;
            size_t gv = ((size_t)bh * HD + row) * Tt + k0 + seg * 8;
            cpa16(base + so,            g_Kh + gk);
            cpa16(base + KT_B + so,     g_Kl + gk);
            cpa16(base + 2 * KT_B + so, g_Vt + gv);
        }
        CP_COMMIT();
    };

    loadKV(0);
    if (n_kv > 1) loadKV(1);

    float m0r = -1e30f, m1r = -1e30f, l0r = 0.f, l1r = 0.f;
    float accO[8][4];
#pragma unroll
    for (int na = 0; na < 8; na++)
#pragma unroll
        for (int j = 0; j < 4; j++) accO[na][j] = 0.f;

    for (int kt = 0; kt < n_kv; kt++) {
        if (kt + 1 < n_kv) { CP_WAIT(1); } else { CP_WAIT(0); }
        __syncthreads();

        // Last tile covers k in [q0+64, q0+128): fully masked for warps 0-3.
        const bool active = !((kt == n_kv - 1) && (w < 4));

        if (active) {
            const uint32_t base = sT0 + (kt & 1) * ASTG_B;
            const int k0 = kt * 64;

            // ---- S = Q K^T (128x64): main fp32, corrections fp16 ----
            float s[8][4];
            uint32_t sc[8][2];
#pragma unroll
            for (int na = 0; na < 8; na++) {
#pragma unroll
                for (int j = 0; j < 4; j++) s[na][j] = 0.f;
                sc[na][0] = 0u; sc[na][1] = 0u;
            }

#pragma unroll
            for (int ks = 0; ks < 4; ks++) {
                const uint32_t qo = (uint32_t)((w * 16 + arow) * PITCHQ) + ks * 32 + akb;
                uint32_t qh[4], ql[4];
                ldsm_x4(qh[0], qh[1], qh[2], qh[3], sQh + qo);
                ldsm_x4(ql[0], ql[1], ql[2], ql[3], sQl + qo);
#pragma unroll
                for (int pb = 0; pb < 4; pb++) {
                    // skip K-column block if fully beyond this warp's rows
                    if (k0 + pb * 16 <= wmax) {
                        uint32_t kh[4], kl[4];
                        uint32_t bo = (uint32_t)((pb * 16 + brow) * PITCHQ) + ks * 32 + bkb;
                        ldsm_x4(kh[0], kh[1], kh[2], kh[3], base + bo);
                        ldsm_x4(kl[0], kl[1], kl[2], kl[3], base + KT_B + bo);
#pragma unroll
                        for (int n2 = 0; n2 < 2; n2++) {
                            if (k0 + (pb * 2 + n2) * 8 <= wmax) {
                                const int na = pb * 2 + n2;
                                mma_ff32(s[na],  qh, kh[n2 * 2], kh[n2 * 2 + 1]);
                                mma_ff16(sc[na], ql, kh[n2 * 2], kh[n2 * 2 + 1]);
                                mma_ff16(sc[na], qh, kl[n2 * 2], kl[n2 * 2 + 1]);
                            }
                        }
                    }
                }
            }
            // merge corrections
#pragma unroll
            for (int na = 0; na < 8; na++) {
                s[na][0] += h2lo(sc[na][0]);
                s[na][1] += h2hi(sc[na][0]);
                s[na][2] += h2lo(sc[na][1]);
                s[na][3] += h2hi(sc[na][1]);
            }

            // ---- causal mask (covers skipped blocks too: skip => masked) ----
            const int r0 = q0 + w * 16 + gid, r1 = r0 + 8;
            if (k0 + 63 > r0) {
#pragma unroll
                for (int na = 0; na < 8; na++) {
                    int c0 = k0 + na * 8 + tig * 2, c1 = c0 + 1;
                    if (c0 > r0) s[na][0] = -1e30f;
                    if (c1 > r0) s[na][1] = -1e30f;
                    if (c0 > r1) s[na][2] = -1e30f;
                    if (c1 > r1) s[na][3] = -1e30f;
                }
            }

            // ---- online softmax (base 2, MUFU ex2) ----
            float mx0 = -1e30f, mx1 = -1e30f;
#pragma unroll
            for (int na = 0; na < 8; na++) {
                mx0 = fmaxf(mx0, fmaxf(s[na][0], s[na][1]));
                mx1 = fmaxf(mx1, fmaxf(s[na][2], s[na][3]));
            }
            mx0 = fmaxf(mx0, __shfl_xor_sync(0xffffffffu, mx0, 1));
            mx0 = fmaxf(mx0, __shfl_xor_sync(0xffffffffu, mx0, 2));
            mx1 = fmaxf(mx1, __shfl_xor_sync(0xffffffffu, mx1, 1));
            mx1 = fmaxf(mx1, __shfl_xor_sync(0xffffffffu, mx1, 2));
            float mn0 = fmaxf(m0r, mx0), mn1 = fmaxf(m1r, mx1);
            float c0f = ex2f(m0r - mn0), c1f = ex2f(m1r - mn1);
            m0r = mn0; m1r = mn1;

            float rs0 = 0.f, rs1 = 0.f;
            uint32_t pa[8], pb2[8];       // P fp16 packs: rows gid / gid+8
#pragma unroll
            for (int na = 0; na < 8; na++) {
                float p0 = ex2f(s[na][0] - mn0);
                float p1 = ex2f(s[na][1] - mn0);
                float p2 = ex2f(s[na][2] - mn1);
                float p3 = ex2f(s[na][3] - mn1);
                rs0 += p0 + p1; rs1 += p2 + p3;
                pa[na]  = packh2(p0, p1);
                pb2[na] = packh2(p2, p3);
            }
            rs0 += __shfl_xor_sync(0xffffffffu, rs0, 1);
            rs0 += __shfl_xor_sync(0xffffffffu, rs0, 2);
            rs1 += __shfl_xor_sync(0xffffffffu, rs1, 1);
            rs1 += __shfl_xor_sync(0xffffffffu, rs1, 2);
            l0r = l0r * c0f + rs0;
            l1r = l1r * c1f + rs1;
#pragma unroll
            for (int na = 0; na < 8; na++) {
                accO[na][0] *= c0f; accO[na][1] *= c0f;
                accO[na][2] *= c1f; accO[na][3] *= c1f;
            }

            // ---- O += P V  (skip k-chunks where P == 0: fully masked) ----
            const uint32_t vb = base + 2 * KT_B;
#pragma unroll
            for (int ks = 0; ks < 4; ks++) {
                if (k0 + ks * 16 <= wmax) {
                    uint32_t a_p[4] = {pa[2 * ks], pb2[2 * ks],
                                       pa[2 * ks + 1], pb2[2 * ks + 1]};
#pragma unroll
                    for (int pb = 0; pb < 4; pb++) {
                        uint32_t vh[4];
                        uint32_t bo = (uint32_t)((pb * 16 + brow) * PITCHQ) + ks * 32 + bkb;
                        ldsm_x4(vh[0], vh[1], vh[2], vh[3], vb + bo);
#pragma unroll
                        for (int n2 = 0; n2 < 2; n2++)
                            mma_ff32(accO[pb * 2 + n2], a_p, vh[n2 * 2], vh[n2 * 2 + 1]);
                    }
                }
            }
        }

        if (kt + 2 < n_kv) {
            __syncthreads();      // buffer (kt&1) free across all warps
            loadKV(kt + 2);
        }
    }

    // ---- epilogue ----
    const int b = bh >> 4, hh = bh & 15;
    const float inv0 = 1.0f / l0r, inv1 = 1.0f / l1r;
    const int r0 = q0 + w * 16 + gid, r1 = r0 + 8;
#pragma unroll
    for (int na = 0; na < 8; na++) {
        const int col = hh * 64 + na * 8 + tig * 2;
        float2 o0 = make_float2(accO[na][0] * inv0, accO[na][1] * inv0);
        float2 o1 = make_float2(accO[na][2] * inv1, accO[na][3] * inv1);
        *(float2*)&out[((size_t)(b * Tt + r0)) * Dm + col] = o0;
        *(float2*)&out[((size_t)(b * Tt + r1)) * Dm + col] = o1;
    }
}

// ---------------------------------------------------------------------------
extern "C" void kernel_launch(void* const* d_in, const int* in_sizes, int n_in,
                              void* d_out, int out_size)
{
    (void)in_sizes; (void)n_in; (void)out_size;
    const float* x  = (const float*)d_in[0];
    const float* Wq = (const float*)d_in[1];
    const float* bq = (const float*)d_in[2];
    const float* Wk = (const float*)d_in[3];
    const float* bk = (const float*)d_in[4];
    const float* Wv = (const float*)d_in[5];
    const float* bv = (const float*)d_in[6];
    float* out = (float*)d_out;

    const int nblk = (NX4 + 3 * NW4) / 512;     // 5632
    split_all<<<nblk, 256>>>(x, Wq, Wk, Wv);

    cudaFuncSetAttribute(proj_mma_kernel,
                         cudaFuncAttributeMaxDynamicSharedMemorySize, GEMM_SMEM);
    dim3 pg(Mtot / 128, Dm / 128, 3);
    proj_mma_kernel<<<pg, 256, GEMM_SMEM>>>(bq, bk, bv);

    cudaFuncSetAttribute(attn_mma_kernel,
                         cudaFuncAttributeMaxDynamicSharedMemorySize, ATTN_SMEM);
    attn_mma_kernel<<<dim3(16, 64), 256, ATTN_SMEM>>>(out);
}

// round 15
// speedup vs baseline: 1.0491x; 1.0491x over previous
#include <cuda_runtime.h>
#include <cuda_fp16.h>
#include <cstdint>

#define Dm   1024
#define Hn   16
#define HD   64
#define Bb   4
#define Tt   2048
#define BH   (Bb*Hn)
#define Mtot (Bb*Tt)
#define NX4  (Mtot*Dm/4)
#define NW4  (Dm*Dm/4)

// Split-fp16 GEMM operands
__device__ __half g_Xh[(size_t)Mtot * Dm];
__device__ __half g_Xl[(size_t)Mtot * Dm];
__device__ __half g_Wh[(size_t)3 * Dm * Dm];
__device__ __half g_Wl[(size_t)3 * Dm * Dm];
// Projection outputs. Q pre-scaled by 8*log2(e). Q/K split fp16; V^T single fp16.
__device__ __half g_Qh[(size_t)BH * Tt * HD];
__device__ __half g_Ql[(size_t)BH * Tt * HD];
__device__ __half g_Kh[(size_t)BH * Tt * HD];
__device__ __half g_Kl[(size_t)BH * Tt * HD];
__device__ __half g_Vt[(size_t)BH * HD * Tt];

// ---------------------------------------------------------------------------
__device__ __forceinline__ uint32_t smem_u32(const void* p) {
    uint32_t a;
    asm("{ .reg .u64 t; cvta.to.shared.u64 t, %1; cvt.u32.u64 %0, t; }"
        : "=r"(a) : "l"(p));
    return a;
}
__device__ __forceinline__ void cpa16(uint32_t s, const void* g) {
    asm volatile("cp.async.cg.shared.global [%0], [%1], 16;" :: "r"(s), "l"(g));
}
#define CP_COMMIT() asm volatile("cp.async.commit_group;" ::: "memory")
#define CP_WAIT(n)  asm volatile("cp.async.wait_group %0;" :: "n"(n) : "memory")

__device__ __forceinline__ void ldsm_x4(uint32_t& r0, uint32_t& r1,
                                        uint32_t& r2, uint32_t& r3, uint32_t a) {
    asm volatile("ldmatrix.sync.aligned.m8n8.x4.shared.b16 {%0,%1,%2,%3}, [%4];"
                 : "=r"(r0), "=r"(r1), "=r"(r2), "=r"(r3) : "r"(a));
}
// fp16 x fp16 -> fp32 accumulate
__device__ __forceinline__ void mma_ff32(float* c, const uint32_t* a,
                                         uint32_t b0, uint32_t b1) {
    asm volatile(
        "mma.sync.aligned.m16n8k16.row.col.f32.f16.f16.f32 "
        "{%0,%1,%2,%3}, {%4,%5,%6,%7}, {%8,%9}, {%0,%1,%2,%3};"
        : "+f"(c[0]), "+f"(c[1]), "+f"(c[2]), "+f"(c[3])
        : "r"(a[0]), "r"(a[1]), "r"(a[2]), "r"(a[3]), "r"(b0), "r"(b1));
}
// fp16 x fp16 -> fp16 accumulate (correction terms)
__device__ __forceinline__ void mma_ff16(uint32_t* c, const uint32_t* a,
                                         uint32_t b0, uint32_t b1) {
    asm volatile(
        "mma.sync.aligned.m16n8k16.row.col.f16.f16.f16.f16 "
        "{%0,%1}, {%2,%3,%4,%5}, {%6,%7}, {%0,%1};"
        : "+r"(c[0]), "+r"(c[1])
        : "r"(a[0]), "r"(a[1]), "r"(a[2]), "r"(a[3]), "r"(b0), "r"(b1));
}
__device__ __forceinline__ uint32_t packh2(float lo, float hi) {
    __half2 h = __floats2half2_rn(lo, hi);
    return *reinterpret_cast<uint32_t*>(&h);
}
__device__ __forceinline__ float h2lo(uint32_t u) {
    return __half2float(__ushort_as_half((unsigned short)(u & 0xffffu)));
}
__device__ __forceinline__ float h2hi(uint32_t u) {
    return __half2float(__ushort_as_half((unsigned short)(u >> 16)));
}
// guaranteed MUFU path
__device__ __forceinline__ float ex2f(float x) {
    float y;
    asm("ex2.approx.f32 %0, %1;" : "=f"(y) : "f"(x));
    return y;
}

// ---------------------------------------------------------------------------
// Merged split: X, Wq, Wk, Wv -> (hi, lo) fp16. 2 float4 per thread (MLP=2).
// ---------------------------------------------------------------------------
__global__ __launch_bounds__(256) void split_all(
    const float* __restrict__ x, const float* __restrict__ wq,
    const float* __restrict__ wk, const float* __restrict__ wv)
{
#pragma unroll
    for (int jj = 0; jj < 2; jj++) {
        int i = blockIdx.x * 512 + jj * 256 + threadIdx.x;
        const float4* src;
        ushort4 *hi, *lo;
        if (i < NX4) {
            src = (const float4*)x + i;
            hi = (ushort4*)g_Xh + i;
            lo = (ushort4*)g_Xl + i;
        } else {
            int j = i - NX4;
            int w = j >> 18;                 // NW4 = 2^18
            int o = j & (NW4 - 1);
            const float* ws = (w == 0) ? wq : (w == 1) ? wk : wv;
            src = (const float4*)ws + o;
            hi = (ushort4*)(g_Wh + (size_t)w * Dm * Dm) + o;
            lo = (ushort4*)(g_Wl + (size_t)w * Dm * Dm) + o;
        }
        float4 v = *src;
        float f[4] = {v.x, v.y, v.z, v.w};
        unsigned short h[4], l[4];
#pragma unroll
        for (int j = 0; j < 4; j++) {
            __half hb = __float2half_rn(f[j]);
            __half lb = __float2half_rn(f[j] - __half2float(hb));
            h[j] = __half_as_ushort(hb);
            l[j] = __half_as_ushort(lb);
        }
        *hi = make_ushort4(h[0], h[1], h[2], h[3]);
        *lo = make_ushort4(l[0], l[1], l[2], l[3]);
    }
}

// ---------------------------------------------------------------------------
// Projection GEMM (HMMA split-fp16). 128x128 tile, BK=32, 2-stage cp.async,
// 2 CTAs/SM. Units: Q,K -> XhWh + XlWh + XhWl (3 each);  V -> XhWh only (1).
// ---------------------------------------------------------------------------
#define BKp      32
#define NSTp     (Dm / BKp)         // 32
#define PITCH_P  80
#define TILE_P   (128 * PITCH_P)    // 10240
#define STG_P    (4 * TILE_P)       // 40960
#define GEMM_SMEM (2 * STG_P)       // 81920

__global__ __launch_bounds__(256, 2) void proj_mma_kernel(
    const float* __restrict__ bq, const float* __restrict__ bk,
    const float* __restrict__ bv)
{
    extern __shared__ char smem[];
    const int tid  = threadIdx.x;
    const int z    = blockIdx.z;
    const int m0   = blockIdx.x * 128;
    const int n0   = blockIdx.y * 128;

    const uint4* Xh4 = (const uint4*)g_Xh;
    const uint4* Xl4 = (const uint4*)g_Xl;
    const uint4* Wh4 = (const uint4*)(g_Wh + (size_t)z * Dm * Dm);
    const uint4* Wl4 = (const uint4*)(g_Wl + (size_t)z * Dm * Dm);
    const float* bias = (z == 0) ? bq : (z == 1) ? bk : bv;
    __half* OutH = (z == 0) ? g_Qh : g_Kh;
    __half* OutL = (z == 0) ? g_Ql : g_Kl;

    const uint32_t sb = smem_u32(smem);
    const int warp = tid >> 5, lane = tid & 31;
    const int wm = warp >> 2;
    const int wn = warp & 3;
    const int a_row = wm * 64 + (lane & 7) + ((lane >> 3) & 1) * 8;
    const uint32_t a_kb = ((lane >> 4) & 1) * 16;
    const int b_row = wn * 32 + (lane & 7) + ((lane >> 4) & 1) * 8;
    const uint32_t b_kb = ((lane >> 3) & 1) * 16;

    float acc[4][4][4];
    uint32_t ch[4][4][2];
#pragma unroll
    for (int i = 0; i < 4; i++)
#pragma unroll
        for (int j = 0; j < 4; j++) {
#pragma unroll
            for (int k = 0; k < 4; k++) acc[i][j][k] = 0.f;
            ch[i][j][0] = 0u; ch[i][j][1] = 0u;
        }

    auto issue_stage = [&](int s) {
        const uint32_t base = sb + (s & 1) * STG_P;
        const int kseg0 = s * (BKp / 8);
#pragma unroll
        for (int j = 0; j < 2; j++) {
            int idx = tid + 256 * j;
            int row = idx >> 2, seg = idx & 3;
            uint32_t so = (uint32_t)(row * PITCH_P + seg * 16);
            size_t ga = (size_t)(m0 + row) * 128 + kseg0 + seg;
            size_t gb = (size_t)(n0 + row) * 128 + kseg0 + seg;
            cpa16(base + so,              Xh4 + ga);
            cpa16(base + 2 * TILE_P + so, Wh4 + gb);
            if (z != 2) {
                cpa16(base + TILE_P + so,     Xl4 + ga);
                cpa16(base + 3 * TILE_P + so, Wl4 + gb);
            }
        }
        CP_COMMIT();
    };

    issue_stage(0);

    for (int s = 0; s < NSTp; s++) {
        if (s + 1 < NSTp) { issue_stage(s + 1); CP_WAIT(1); }
        else              { CP_WAIT(0); }
        __syncthreads();

        const uint32_t base = sb + (s & 1) * STG_P;
        const uint32_t Ah = base, Al = base + TILE_P;
        const uint32_t Bh = base + 2 * TILE_P, Bl = base + 3 * TILE_P;

#pragma unroll
        for (int ks = 0; ks < 2; ks++) {
            const uint32_t ko = ks * 32;
            uint32_t af[4][4], tf[4][4], bf[2][4];
#pragma unroll
            for (int ma = 0; ma < 4; ma++) {
                uint32_t ao = (uint32_t)((a_row + ma * 16) * PITCH_P) + ko + a_kb;
                ldsm_x4(af[ma][0], af[ma][1], af[ma][2], af[ma][3], Ah + ao);
            }
#pragma unroll
            for (int pb = 0; pb < 2; pb++) {
                uint32_t bo = (uint32_t)((b_row + pb * 16) * PITCH_P) + ko + b_kb;
                ldsm_x4(bf[pb][0], bf[pb][1], bf[pb][2], bf[pb][3], Bh + bo);
            }
            // main: Xh * Wh -> fp32 acc
#pragma unroll
            for (int ma = 0; ma < 4; ma++)
#pragma unroll
                for (int na = 0; na < 4; na++)
                    mma_ff32(acc[ma][na], af[ma],
                             bf[na >> 1][(na & 1) * 2], bf[na >> 1][(na & 1) * 2 + 1]);
            if (z != 2) {
                // corr: Xl * Wh -> fp16 acc
#pragma unroll
                for (int ma = 0; ma < 4; ma++) {
                    uint32_t ao = (uint32_t)((a_row + ma * 16) * PITCH_P) + ko + a_kb;
                    ldsm_x4(tf[ma][0], tf[ma][1], tf[ma][2], tf[ma][3], Al + ao);
                }
#pragma unroll
                for (int ma = 0; ma < 4; ma++)
#pragma unroll
                    for (int na = 0; na < 4; na++)
                        mma_ff16(ch[ma][na], tf[ma],
                                 bf[na >> 1][(na & 1) * 2], bf[na >> 1][(na & 1) * 2 + 1]);
                // corr: Xh * Wl -> fp16 acc
#pragma unroll
                for (int pb = 0; pb < 2; pb++) {
                    uint32_t bo = (uint32_t)((b_row + pb * 16) * PITCH_P) + ko + b_kb;
                    ldsm_x4(bf[pb][0], bf[pb][1], bf[pb][2], bf[pb][3], Bl + bo);
                }
#pragma unroll
                for (int ma = 0; ma < 4; ma++)
#pragma unroll
                    for (int na = 0; na < 4; na++)
                        mma_ff16(ch[ma][na], af[ma],
                                 bf[na >> 1][(na & 1) * 2], bf[na >> 1][(na & 1) * 2 + 1]);
            }
        }
        __syncthreads();
    }

    // epilogue: merge corrections, +bias, (Q: x 8*log2e), store
    const int gid = lane >> 2, tig = lane & 3;
    const float qscale = (z == 0) ? 11.541560327111707f : 1.0f;   // 8*log2(e)
#pragma unroll
    for (int ma = 0; ma < 4; ma++) {
#pragma unroll
        for (int na = 0; na < 4; na++) {
            const int col = n0 + wn * 32 + na * 8 + tig * 2;
            const float2 bv2 = *(const float2*)&bias[col];
            const int hh = col >> 6, d = col & 63;
            float c4[4];
            c4[0] = acc[ma][na][0] + h2lo(ch[ma][na][0]);
            c4[1] = acc[ma][na][1] + h2hi(ch[ma][na][0]);
            c4[2] = acc[ma][na][2] + h2lo(ch[ma][na][1]);
            c4[3] = acc[ma][na][3] + h2hi(ch[ma][na][1]);
#pragma unroll
            for (int half = 0; half < 2; half++) {
                const int row = m0 + wm * 64 + ma * 16 + gid + half * 8;
                const int t = row & 2047;
                const int bhidx = ((row >> 11) << 4) + hh;
                float v0 = (c4[half * 2 + 0] + bv2.x) * qscale;
                float v1 = (c4[half * 2 + 1] + bv2.y) * qscale;
                __half h0 = __float2half_rn(v0);
                __half h1 = __float2half_rn(v1);
                if (z < 2) {
                    __half l0 = __float2half_rn(v0 - __half2float(h0));
                    __half l1 = __float2half_rn(v1 - __half2float(h1));
                    size_t ix = ((size_t)bhidx * Tt + t) * HD + d;
                    uint32_t ph = ((uint32_t)__half_as_ushort(h1) << 16) |
                                   __half_as_ushort(h0);
                    uint32_t pl = ((uint32_t)__half_as_ushort(l1) << 16) |
                                   __half_as_ushort(l0);
                    *(uint32_t*)&OutH[ix] = ph;
                    *(uint32_t*)&OutL[ix] = pl;
                } else {
                    size_t ix = ((size_t)bhidx * HD + d) * Tt + t;
                    g_Vt[ix]      = h0;
                    g_Vt[ix + Tt] = h1;
                }
            }
        }
    }
}

// ---------------------------------------------------------------------------
// Flash attention, HMMA fp16, base-2 softmax (Q pre-scaled 8*log2e).
// S: QhKh (fp32 acc) + QlKh + QhKl (fp16 acc). PV: single product, P & V fp16.
// BQ=128 (8 warps x M16), BKV=64, 2-stage cp.async ring, 2 CTAs/SM.
// Final diagonal KV tile is fully masked for warps 0-3 -> skipped (identity).
// ---------------------------------------------------------------------------
#define PITCHQ  144
#define AQ_B    (128 * PITCHQ)        // 18432 per Q array
#define KT_B    (64 * PITCHQ)         // 9216 per K array (64 t-rows x 64 d)
#define VT_B    (64 * PITCHQ)         // 9216 V^T (64 d-rows x 64 t)
#define ASTG_B  (2 * KT_B + VT_B)     // 27648
#define ATTN_SMEM (2 * AQ_B + 2 * ASTG_B)   // 92160

__global__ __launch_bounds__(256, 2) void attn_mma_kernel(float* __restrict__ out)
{
    extern __shared__ char smem[];
    const int tid  = threadIdx.x;
    const int w    = tid >> 5, lane = tid & 31;
    const int qi   = (int)gridDim.x - 1 - (int)blockIdx.x;   // long CTAs first
    const int bh   = blockIdx.y;
    const int q0   = qi * 128;
    const int n_kv = 2 * (qi + 1);

    const uint32_t sb  = smem_u32(smem);
    const uint32_t sQh = sb, sQl = sb + AQ_B;
    const uint32_t sT0 = sb + 2 * AQ_B;

    const int gid = lane >> 2, tig = lane & 3;
    const int arow = (lane & 7) + ((lane >> 3) & 1) * 8;
    const uint32_t akb = ((lane >> 4) & 1) * 16;
    const int brow = (lane & 7) + ((lane >> 4) & 1) * 8;
    const uint32_t bkb = ((lane >> 3) & 1) * 16;

    // Q: 128 rows x 64 fp16 (hi+lo) — joins commit group 0
#pragma unroll
    for (int j = 0; j < 4; j++) {
        int idx = tid + 256 * j;
        int row = idx >> 3, seg = idx & 7;
        uint32_t so = (uint32_t)(row * PITCHQ + seg * 16);
        size_t g = ((size_t)bh * Tt + q0 + row) * HD + seg * 8;
        cpa16(sQh + so, g_Qh + g);
        cpa16(sQl + so, g_Ql + g);
    }
    auto loadKV = [&](int kt) {
        const uint32_t base = sT0 + (kt & 1) * ASTG_B;
        const int k0 = kt * 64;
#pragma unroll
        for (int j = 0; j < 2; j++) {
            int idx = tid + 256 * j;
            int row = idx >> 3, seg = idx & 7;
            uint32_t so = (uint32_t)(row * PITCHQ + seg * 16);
            size_t gk = ((size_t)bh * Tt + k0 + row) * HD + seg * 8;
            size_t gv = ((size_t)bh * HD + row) * Tt + k0 + seg * 8;
            cpa16(base + so,            g_Kh + gk);
            cpa16(base + KT_B + so,     g_Kl + gk);
            cpa16(base + 2 * KT_B + so, g_Vt + gv);
        }
        CP_COMMIT();
    };

    loadKV(0);
    if (n_kv > 1) loadKV(1);

    float m0r = -1e30f, m1r = -1e30f, l0r = 0.f, l1r = 0.f;
    float accO[8][4];
#pragma unroll
    for (int na = 0; na < 8; na++)
#pragma unroll
        for (int j = 0; j < 4; j++) accO[na][j] = 0.f;

    for (int kt = 0; kt < n_kv; kt++) {
        if (kt + 1 < n_kv) { CP_WAIT(1); } else { CP_WAIT(0); }
        __syncthreads();

        // Last diagonal tile covers k in [q0+64, q0+128): fully masked for
        // warps 0-3 (q rows q0..q0+63). Skipping their compute is an identity
        // (P rows all zero; m/l/accO unchanged).
        const bool active = !((kt == n_kv - 1) && (w < 4));

        if (active) {
            const uint32_t base = sT0 + (kt & 1) * ASTG_B;
            const int k0 = kt * 64;

            // ---- S = Q K^T (128x64): main fp32, corrections fp16 ----
            float s[8][4];
            uint32_t sc[8][2];
#pragma unroll
            for (int na = 0; na < 8; na++) {
#pragma unroll
                for (int j = 0; j < 4; j++) s[na][j] = 0.f;
                sc[na][0] = 0u; sc[na][1] = 0u;
            }

#pragma unroll
            for (int ks = 0; ks < 4; ks++) {
                const uint32_t qo = (uint32_t)((w * 16 + arow) * PITCHQ) + ks * 32 + akb;
                uint32_t qh[4], ql[4];
                ldsm_x4(qh[0], qh[1], qh[2], qh[3], sQh + qo);
                ldsm_x4(ql[0], ql[1], ql[2], ql[3], sQl + qo);
#pragma unroll
                for (int pb = 0; pb < 4; pb++) {
                    uint32_t kh[4], kl[4];
                    uint32_t bo = (uint32_t)((pb * 16 + brow) * PITCHQ) + ks * 32 + bkb;
                    ldsm_x4(kh[0], kh[1], kh[2], kh[3], base + bo);
                    ldsm_x4(kl[0], kl[1], kl[2], kl[3], base + KT_B + bo);
#pragma unroll
                    for (int n2 = 0; n2 < 2; n2++) {
                        const int na = pb * 2 + n2;
                        mma_ff32(s[na],  qh, kh[n2 * 2], kh[n2 * 2 + 1]);
                        mma_ff16(sc[na], ql, kh[n2 * 2], kh[n2 * 2 + 1]);
                        mma_ff16(sc[na], qh, kl[n2 * 2], kl[n2 * 2 + 1]);
                    }
                }
            }
            // merge corrections
#pragma unroll
            for (int na = 0; na < 8; na++) {
                s[na][0] += h2lo(sc[na][0]);
                s[na][1] += h2hi(sc[na][0]);
                s[na][2] += h2lo(sc[na][1]);
                s[na][3] += h2hi(sc[na][1]);
            }

            // ---- causal mask ----
            const int r0 = q0 + w * 16 + gid, r1 = r0 + 8;
            if (k0 + 63 > r0) {
#pragma unroll
                for (int na = 0; na < 8; na++) {
                    int c0 = k0 + na * 8 + tig * 2, c1 = c0 + 1;
                    if (c0 > r0) s[na][0] = -1e30f;
                    if (c1 > r0) s[na][1] = -1e30f;
                    if (c0 > r1) s[na][2] = -1e30f;
                    if (c1 > r1) s[na][3] = -1e30f;
                }
            }

            // ---- online softmax (base 2, MUFU ex2) ----
            float mx0 = -1e30f, mx1 = -1e30f;
#pragma unroll
            for (int na = 0; na < 8; na++) {
                mx0 = fmaxf(mx0, fmaxf(s[na][0], s[na][1]));
                mx1 = fmaxf(mx1, fmaxf(s[na][2], s[na][3]));
            }
            mx0 = fmaxf(mx0, __shfl_xor_sync(0xffffffffu, mx0, 1));
            mx0 = fmaxf(mx0, __shfl_xor_sync(0xffffffffu, mx0, 2));
            mx1 = fmaxf(mx1, __shfl_xor_sync(0xffffffffu, mx1, 1));
            mx1 = fmaxf(mx1, __shfl_xor_sync(0xffffffffu, mx1, 2));
            float mn0 = fmaxf(m0r, mx0), mn1 = fmaxf(m1r, mx1);
            float c0f = ex2f(m0r - mn0), c1f = ex2f(m1r - mn1);
            m0r = mn0; m1r = mn1;

            float rs0 = 0.f, rs1 = 0.f;
            uint32_t pa[8], pb2[8];       // P fp16 packs: rows gid / gid+8
#pragma unroll
            for (int na = 0; na < 8; na++) {
                float p0 = ex2f(s[na][0] - mn0);
                float p1 = ex2f(s[na][1] - mn0);
                float p2 = ex2f(s[na][2] - mn1);
                float p3 = ex2f(s[na][3] - mn1);
                rs0 += p0 + p1; rs1 += p2 + p3;
                pa[na]  = packh2(p0, p1);
                pb2[na] = packh2(p2, p3);
            }
            rs0 += __shfl_xor_sync(0xffffffffu, rs0, 1);
            rs0 += __shfl_xor_sync(0xffffffffu, rs0, 2);
            rs1 += __shfl_xor_sync(0xffffffffu, rs1, 1);
            rs1 += __shfl_xor_sync(0xffffffffu, rs1, 2);
            l0r = l0r * c0f + rs0;
            l1r = l1r * c1f + rs1;
#pragma unroll
            for (int na = 0; na < 8; na++) {
                accO[na][0] *= c0f; accO[na][1] *= c0f;
                accO[na][2] *= c1f; accO[na][3] *= c1f;
            }

            // ---- O += P V  (single product, P & V fp16; K-dim = 64) ----
            const uint32_t vb = base + 2 * KT_B;
#pragma unroll
            for (int ks = 0; ks < 4; ks++) {
                uint32_t a_p[4] = {pa[2 * ks], pb2[2 * ks], pa[2 * ks + 1], pb2[2 * ks + 1]};
#pragma unroll
                for (int pb = 0; pb < 4; pb++) {
                    uint32_t vh[4];
                    uint32_t bo = (uint32_t)((pb * 16 + brow) * PITCHQ) + ks * 32 + bkb;
                    ldsm_x4(vh[0], vh[1], vh[2], vh[3], vb + bo);
#pragma unroll
                    for (int n2 = 0; n2 < 2; n2++)
                        mma_ff32(accO[pb * 2 + n2], a_p, vh[n2 * 2], vh[n2 * 2 + 1]);
                }
            }
        }

        if (kt + 2 < n_kv) {
            __syncthreads();      // buffer (kt&1) free across all warps
            loadKV(kt + 2);
        }
    }

    // ---- epilogue ----
    const int b = bh >> 4, hh = bh & 15;
    const float inv0 = 1.0f / l0r, inv1 = 1.0f / l1r;
    const int r0 = q0 + w * 16 + gid, r1 = r0 + 8;
#pragma unroll
    for (int na = 0; na < 8; na++) {
        const int col = hh * 64 + na * 8 + tig * 2;
        float2 o0 = make_float2(accO[na][0] * inv0, accO[na][1] * inv0);
        float2 o1 = make_float2(accO[na][2] * inv1, accO[na][3] * inv1);
        *(float2*)&out[((size_t)(b * Tt + r0)) * Dm + col] = o0;
        *(float2*)&out[((size_t)(b * Tt + r1)) * Dm + col] = o1;
    }
}

// ---------------------------------------------------------------------------
extern "C" void kernel_launch(void* const* d_in, const int* in_sizes, int n_in,
                              void* d_out, int out_size)
{
    (void)in_sizes; (void)n_in; (void)out_size;
    const float* x  = (const float*)d_in[0];
    const float* Wq = (const float*)d_in[1];
    const float* bq = (const float*)d_in[2];
    const float* Wk = (const float*)d_in[3];
    const float* bk = (const float*)d_in[4];
    const float* Wv = (const float*)d_in[5];
    const float* bv = (const float*)d_in[6];
    float* out = (float*)d_out;

    const int nblk = (NX4 + 3 * NW4) / 512;     // 5632
    split_all<<<nblk, 256>>>(x, Wq, Wk, Wv);

    cudaFuncSetAttribute(proj_mma_kernel,
                         cudaFuncAttributeMaxDynamicSharedMemorySize, GEMM_SMEM);
    dim3 pg(Mtot / 128, Dm / 128, 3);
    proj_mma_kernel<<<pg, 256, GEMM_SMEM>>>(bq, bk, bv);

    cudaFuncSetAttribute(attn_mma_kernel,
                         cudaFuncAttributeMaxDynamicSharedMemorySize, ATTN_SMEM);
    attn_mma_kernel<<<dim3(16, 64), 256, ATTN_SMEM>>>(out);
}

// round 16
// speedup vs baseline: 1.0671x; 1.0172x over previous
#include <cuda_runtime.h>
#include <cuda_fp16.h>
#include <cstdint>

#define Dm   1024
#define Hn   16
#define HD   64
#define Bb   4
#define Tt   2048
#define BH   (Bb*Hn)
#define Mtot (Bb*Tt)
#define NX4  (Mtot*Dm/4)
#define NW4  (Dm*Dm/4)

// Split-fp16 GEMM operands
__device__ __half g_Xh[(size_t)Mtot * Dm];
__device__ __half g_Xl[(size_t)Mtot * Dm];
__device__ __half g_Wh[(size_t)3 * Dm * Dm];
__device__ __half g_Wl[(size_t)3 * Dm * Dm];
// Projection outputs. Q pre-scaled by 8*log2(e). Q/K split fp16; V^T single fp16.
__device__ __half g_Qh[(size_t)BH * Tt * HD];
__device__ __half g_Ql[(size_t)BH * Tt * HD];
__device__ __half g_Kh[(size_t)BH * Tt * HD];
__device__ __half g_Kl[(size_t)BH * Tt * HD];
__device__ __half g_Vt[(size_t)BH * HD * Tt];

// ---------------------------------------------------------------------------
__device__ __forceinline__ uint32_t smem_u32(const void* p) {
    uint32_t a;
    asm("{ .reg .u64 t; cvta.to.shared.u64 t, %1; cvt.u32.u64 %0, t; }"
        : "=r"(a) : "l"(p));
    return a;
}
__device__ __forceinline__ void cpa16(uint32_t s, const void* g) {
    asm volatile("cp.async.cg.shared.global [%0], [%1], 16;" :: "r"(s), "l"(g));
}
#define CP_COMMIT() asm volatile("cp.async.commit_group;" ::: "memory")
#define CP_WAIT(n)  asm volatile("cp.async.wait_group %0;" :: "n"(n) : "memory")

__device__ __forceinline__ void ldsm_x4(uint32_t& r0, uint32_t& r1,
                                        uint32_t& r2, uint32_t& r3, uint32_t a) {
    asm volatile("ldmatrix.sync.aligned.m8n8.x4.shared.b16 {%0,%1,%2,%3}, [%4];"
                 : "=r"(r0), "=r"(r1), "=r"(r2), "=r"(r3) : "r"(a));
}
// fp16 x fp16 -> fp32 accumulate
__device__ __forceinline__ void mma_ff32(float* c, const uint32_t* a,
                                         uint32_t b0, uint32_t b1) {
    asm volatile(
        "mma.sync.aligned.m16n8k16.row.col.f32.f16.f16.f32 "
        "{%0,%1,%2,%3}, {%4,%5,%6,%7}, {%8,%9}, {%0,%1,%2,%3};"
        : "+f"(c[0]), "+f"(c[1]), "+f"(c[2]), "+f"(c[3])
        : "r"(a[0]), "r"(a[1]), "r"(a[2]), "r"(a[3]), "r"(b0), "r"(b1));
}
// fp16 x fp16 -> fp16 accumulate (correction terms)
__device__ __forceinline__ void mma_ff16(uint32_t* c, const uint32_t* a,
                                         uint32_t b0, uint32_t b1) {
    asm volatile(
        "mma.sync.aligned.m16n8k16.row.col.f16.f16.f16.f16 "
        "{%0,%1}, {%2,%3,%4,%5}, {%6,%7}, {%0,%1};"
        : "+r"(c[0]), "+r"(c[1])
        : "r"(a[0]), "r"(a[1]), "r"(a[2]), "r"(a[3]), "r"(b0), "r"(b1));
}
__device__ __forceinline__ uint32_t packh2(float lo, float hi) {
    __half2 h = __floats2half2_rn(lo, hi);
    return *reinterpret_cast<uint32_t*>(&h);
}
__device__ __forceinline__ float h2lo(uint32_t u) {
    return __half2float(__ushort_as_half((unsigned short)(u & 0xffffu)));
}
__device__ __forceinline__ float h2hi(uint32_t u) {
    return __half2float(__ushort_as_half((unsigned short)(u >> 16)));
}
// guaranteed MUFU path
__device__ __forceinline__ float ex2f(float x) {
    float y;
    asm("ex2.approx.f32 %0, %1;" : "=f"(y) : "f"(x));
    return y;
}

// ---------------------------------------------------------------------------
// Merged split: X, Wq, Wk, Wv -> (hi, lo) fp16. 2 float4 per thread (MLP=2).
// ---------------------------------------------------------------------------
__global__ __launch_bounds__(256) void split_all(
    const float* __restrict__ x, const float* __restrict__ wq,
    const float* __restrict__ wk, const float* __restrict__ wv)
{
#pragma unroll
    for (int jj = 0; jj < 2; jj++) {
        int i = blockIdx.x * 512 + jj * 256 + threadIdx.x;
        const float4* src;
        ushort4 *hi, *lo;
        if (i < NX4) {
            src = (const float4*)x + i;
            hi = (ushort4*)g_Xh + i;
            lo = (ushort4*)g_Xl + i;
        } else {
            int j = i - NX4;
            int w = j >> 18;                 // NW4 = 2^18
            int o = j & (NW4 - 1);
            const float* ws = (w == 0) ? wq : (w == 1) ? wk : wv;
            src = (const float4*)ws + o;
            hi = (ushort4*)(g_Wh + (size_t)w * Dm * Dm) + o;
            lo = (ushort4*)(g_Wl + (size_t)w * Dm * Dm) + o;
        }
        float4 v = *src;
        float f[4] = {v.x, v.y, v.z, v.w};
        unsigned short h[4], l[4];
#pragma unroll
        for (int j = 0; j < 4; j++) {
            __half hb = __float2half_rn(f[j]);
            __half lb = __float2half_rn(f[j] - __half2float(hb));
            h[j] = __half_as_ushort(hb);
            l[j] = __half_as_ushort(lb);
        }
        *hi = make_ushort4(h[0], h[1], h[2], h[3]);
        *lo = make_ushort4(l[0], l[1], l[2], l[3]);
    }
}

// ---------------------------------------------------------------------------
// Q/K projection GEMM (HMMA split-fp16). 128x128 tile, BK=32, 2-stage
// cp.async, 2 CTAs/SM. Units: XhWh (fp32 acc) + XlWh + XhWl (fp16 acc).
// ---------------------------------------------------------------------------
#define BKp      32
#define NSTp     (Dm / BKp)         // 32
#define PITCH_P  80
#define TILE_P   (128 * PITCH_P)    // 10240
#define STG_P    (4 * TILE_P)       // 40960
#define GEMM_SMEM (2 * STG_P)       // 81920

__global__ __launch_bounds__(256, 2) void proj_mma_kernel(
    const float* __restrict__ bq, const float* __restrict__ bk)
{
    extern __shared__ char smem[];
    const int tid  = threadIdx.x;
    const int z    = blockIdx.z;    // 0 = Q, 1 = K
    const int m0   = blockIdx.x * 128;
    const int n0   = blockIdx.y * 128;

    const uint4* Xh4 = (const uint4*)g_Xh;
    const uint4* Xl4 = (const uint4*)g_Xl;
    const uint4* Wh4 = (const uint4*)(g_Wh + (size_t)z * Dm * Dm);
    const uint4* Wl4 = (const uint4*)(g_Wl + (size_t)z * Dm * Dm);
    const float* bias = (z == 0) ? bq : bk;
    __half* OutH = (z == 0) ? g_Qh : g_Kh;
    __half* OutL = (z == 0) ? g_Ql : g_Kl;

    const uint32_t sb = smem_u32(smem);
    const int warp = tid >> 5, lane = tid & 31;
    const int wm = warp >> 2;
    const int wn = warp & 3;
    const int a_row = wm * 64 + (lane & 7) + ((lane >> 3) & 1) * 8;
    const uint32_t a_kb = ((lane >> 4) & 1) * 16;
    const int b_row = wn * 32 + (lane & 7) + ((lane >> 4) & 1) * 8;
    const uint32_t b_kb = ((lane >> 3) & 1) * 16;

    float acc[4][4][4];
    uint32_t ch[4][4][2];
#pragma unroll
    for (int i = 0; i < 4; i++)
#pragma unroll
        for (int j = 0; j < 4; j++) {
#pragma unroll
            for (int k = 0; k < 4; k++) acc[i][j][k] = 0.f;
            ch[i][j][0] = 0u; ch[i][j][1] = 0u;
        }

    auto issue_stage = [&](int s) {
        const uint32_t base = sb + (s & 1) * STG_P;
        const int kseg0 = s * (BKp / 8);
#pragma unroll
        for (int j = 0; j < 2; j++) {
            int idx = tid + 256 * j;
            int row = idx >> 2, seg = idx & 3;
            uint32_t so = (uint32_t)(row * PITCH_P + seg * 16);
            size_t ga = (size_t)(m0 + row) * 128 + kseg0 + seg;
            size_t gb = (size_t)(n0 + row) * 128 + kseg0 + seg;
            cpa16(base + so,              Xh4 + ga);
            cpa16(base + 2 * TILE_P + so, Wh4 + gb);
            cpa16(base + TILE_P + so,     Xl4 + ga);
            cpa16(base + 3 * TILE_P + so, Wl4 + gb);
        }
        CP_COMMIT();
    };

    issue_stage(0);

    for (int s = 0; s < NSTp; s++) {
        if (s + 1 < NSTp) { issue_stage(s + 1); CP_WAIT(1); }
        else              { CP_WAIT(0); }
        __syncthreads();

        const uint32_t base = sb + (s & 1) * STG_P;
        const uint32_t Ah = base, Al = base + TILE_P;
        const uint32_t Bh = base + 2 * TILE_P, Bl = base + 3 * TILE_P;

#pragma unroll
        for (int ks = 0; ks < 2; ks++) {
            const uint32_t ko = ks * 32;
            uint32_t af[4][4], tf[4][4], bf[2][4];
#pragma unroll
            for (int ma = 0; ma < 4; ma++) {
                uint32_t ao = (uint32_t)((a_row + ma * 16) * PITCH_P) + ko + a_kb;
                ldsm_x4(af[ma][0], af[ma][1], af[ma][2], af[ma][3], Ah + ao);
            }
#pragma unroll
            for (int pb = 0; pb < 2; pb++) {
                uint32_t bo = (uint32_t)((b_row + pb * 16) * PITCH_P) + ko + b_kb;
                ldsm_x4(bf[pb][0], bf[pb][1], bf[pb][2], bf[pb][3], Bh + bo);
            }
            // main: Xh * Wh -> fp32 acc
#pragma unroll
            for (int ma = 0; ma < 4; ma++)
#pragma unroll
                for (int na = 0; na < 4; na++)
                    mma_ff32(acc[ma][na], af[ma],
                             bf[na >> 1][(na & 1) * 2], bf[na >> 1][(na & 1) * 2 + 1]);
            // corr: Xl * Wh -> fp16 acc
#pragma unroll
            for (int ma = 0; ma < 4; ma++) {
                uint32_t ao = (uint32_t)((a_row + ma * 16) * PITCH_P) + ko + a_kb;
                ldsm_x4(tf[ma][0], tf[ma][1], tf[ma][2], tf[ma][3], Al + ao);
            }
#pragma unroll
            for (int ma = 0; ma < 4; ma++)
#pragma unroll
                for (int na = 0; na < 4; na++)
                    mma_ff16(ch[ma][na], tf[ma],
                             bf[na >> 1][(na & 1) * 2], bf[na >> 1][(na & 1) * 2 + 1]);
            // corr: Xh * Wl -> fp16 acc
#pragma unroll
            for (int pb = 0; pb < 2; pb++) {
                uint32_t bo = (uint32_t)((b_row + pb * 16) * PITCH_P) + ko + b_kb;
                ldsm_x4(bf[pb][0], bf[pb][1], bf[pb][2], bf[pb][3], Bl + bo);
            }
#pragma unroll
            for (int ma = 0; ma < 4; ma++)
#pragma unroll
                for (int na = 0; na < 4; na++)
                    mma_ff16(ch[ma][na], af[ma],
                             bf[na >> 1][(na & 1) * 2], bf[na >> 1][(na & 1) * 2 + 1]);
        }
        __syncthreads();
    }

    // epilogue: merge corrections, +bias, (Q: x 8*log2e), store split fp16
    const int gid = lane >> 2, tig = lane & 3;
    const float qscale = (z == 0) ? 11.541560327111707f : 1.0f;   // 8*log2(e)
#pragma unroll
    for (int ma = 0; ma < 4; ma++) {
#pragma unroll
        for (int na = 0; na < 4; na++) {
            const int col = n0 + wn * 32 + na * 8 + tig * 2;
            const float2 bv2 = *(const float2*)&bias[col];
            const int hh = col >> 6, d = col & 63;
            float c4[4];
            c4[0] = acc[ma][na][0] + h2lo(ch[ma][na][0]);
            c4[1] = acc[ma][na][1] + h2hi(ch[ma][na][0]);
            c4[2] = acc[ma][na][2] + h2lo(ch[ma][na][1]);
            c4[3] = acc[ma][na][3] + h2hi(ch[ma][na][1]);
#pragma unroll
            for (int half = 0; half < 2; half++) {
                const int row = m0 + wm * 64 + ma * 16 + gid + half * 8;
                const int t = row & 2047;
                const int bhidx = ((row >> 11) << 4) + hh;
                float v0 = (c4[half * 2 + 0] + bv2.x) * qscale;
                float v1 = (c4[half * 2 + 1] + bv2.y) * qscale;
                __half h0 = __float2half_rn(v0);
                __half h1 = __float2half_rn(v1);
                __half l0 = __float2half_rn(v0 - __half2float(h0));
                __half l1 = __float2half_rn(v1 - __half2float(h1));
                size_t ix = ((size_t)bhidx * Tt + t) * HD + d;
                uint32_t ph = ((uint32_t)__half_as_ushort(h1) << 16) |
                               __half_as_ushort(h0);
                uint32_t pl = ((uint32_t)__half_as_ushort(l1) << 16) |
                               __half_as_ushort(l0);
                *(uint32_t*)&OutH[ix] = ph;
                *(uint32_t*)&OutL[ix] = pl;
            }
        }
    }
}

// ---------------------------------------------------------------------------
// V projection (single product XhWh, fp32 acc). BK=64, 16 stages, 2-stage
// cp.async, 2 CTAs/SM. Same k-accumulation order as BK=32 -> bit-identical V.
// ---------------------------------------------------------------------------
#define PITCH_V  144
#define TILE_V   (128 * PITCH_V)    // 18432
#define STG_V    (2 * TILE_V)       // 36864
#define GEMM_V_SMEM (2 * STG_V)     // 73728

__global__ __launch_bounds__(256, 2) void proj_v_kernel(const float* __restrict__ bv)
{
    extern __shared__ char smem[];
    const int tid = threadIdx.x;
    const int m0  = blockIdx.x * 128;
    const int n0  = blockIdx.y * 128;

    const uint4* Xh4 = (const uint4*)g_Xh;
    const uint4* Wh4 = (const uint4*)(g_Wh + (size_t)2 * Dm * Dm);

    const uint32_t sb = smem_u32(smem);
    const int warp = tid >> 5, lane = tid & 31;
    const int wm = warp >> 2;
    const int wn = warp & 3;
    const int a_row = wm * 64 + (lane & 7) + ((lane >> 3) & 1) * 8;
    const uint32_t a_kb = ((lane >> 4) & 1) * 16;
    const int b_row = wn * 32 + (lane & 7) + ((lane >> 4) & 1) * 8;
    const uint32_t b_kb = ((lane >> 3) & 1) * 16;

    float acc[4][4][4];
#pragma unroll
    for (int i = 0; i < 4; i++)
#pragma unroll
        for (int j = 0; j < 4; j++)
#pragma unroll
            for (int k = 0; k < 4; k++) acc[i][j][k] = 0.f;

    // stage: Xh + Wh tiles, 128 rows x 8 uint4 segs each = 2048 cp.async
    auto issue_stage = [&](int s) {
        const uint32_t base = sb + (s & 1) * STG_V;
        const int kseg0 = s * 8;          // BK=64 -> 8 uint4 per row
#pragma unroll
        for (int j = 0; j < 4; j++) {
            int idx = tid + 256 * j;
            int row = idx >> 3, seg = idx & 7;
            uint32_t so = (uint32_t)(row * PITCH_V + seg * 16);
            size_t ga = (size_t)(m0 + row) * 128 + kseg0 + seg;
            size_t gb = (size_t)(n0 + row) * 128 + kseg0 + seg;
            cpa16(base + so,          Xh4 + ga);
            cpa16(base + TILE_V + so, Wh4 + gb);
        }
        CP_COMMIT();
    };

    issue_stage(0);

    for (int s = 0; s < 16; s++) {
        if (s + 1 < 16) { issue_stage(s + 1); CP_WAIT(1); }
        else            { CP_WAIT(0); }
        __syncthreads();

        const uint32_t base = sb + (s & 1) * STG_V;
        const uint32_t Ah = base, Bh = base + TILE_V;

#pragma unroll
        for (int ks = 0; ks < 4; ks++) {
            const uint32_t ko = ks * 32;
            uint32_t af[4][4], bf[2][4];
#pragma unroll
            for (int ma = 0; ma < 4; ma++) {
                uint32_t ao = (uint32_t)((a_row + ma * 16) * PITCH_V) + ko + a_kb;
                ldsm_x4(af[ma][0], af[ma][1], af[ma][2], af[ma][3], Ah + ao);
            }
#pragma unroll
            for (int pb = 0; pb < 2; pb++) {
                uint32_t bo = (uint32_t)((b_row + pb * 16) * PITCH_V) + ko + b_kb;
                ldsm_x4(bf[pb][0], bf[pb][1], bf[pb][2], bf[pb][3], Bh + bo);
            }
#pragma unroll
            for (int ma = 0; ma < 4; ma++)
#pragma unroll
                for (int na = 0; na < 4; na++)
                    mma_ff32(acc[ma][na], af[ma],
                             bf[na >> 1][(na & 1) * 2], bf[na >> 1][(na & 1) * 2 + 1]);
        }
        __syncthreads();
    }

    // epilogue: +bias, store V^T single fp16 [bh][d][t]
    const int gid = lane >> 2, tig = lane & 3;
#pragma unroll
    for (int ma = 0; ma < 4; ma++) {
#pragma unroll
        for (int na = 0; na < 4; na++) {
            const int col = n0 + wn * 32 + na * 8 + tig * 2;
            const float2 bv2 = *(const float2*)&bv[col];
            const int hh = col >> 6, d = col & 63;
#pragma unroll
            for (int half = 0; half < 2; half++) {
                const int row = m0 + wm * 64 + ma * 16 + gid + half * 8;
                const int t = row & 2047;
                const int bhidx = ((row >> 11) << 4) + hh;
                float v0 = acc[ma][na][half * 2 + 0] + bv2.x;
                float v1 = acc[ma][na][half * 2 + 1] + bv2.y;
                size_t ix = ((size_t)bhidx * HD + d) * Tt + t;
                g_Vt[ix]      = __float2half_rn(v0);
                g_Vt[ix + Tt] = __float2half_rn(v1);
            }
        }
    }
}

// ---------------------------------------------------------------------------
// Flash attention, HMMA fp16, base-2 softmax (Q pre-scaled 8*log2e).
// S: QhKh (fp32 acc) + QlKh + QhKl (fp16 acc). PV: single product, P & V fp16.
// BQ=128 (8 warps x M16), BKV=64, 2-stage cp.async ring, 2 CTAs/SM.
// Final diagonal KV tile is fully masked for warps 0-3 -> skipped (identity).
// ---------------------------------------------------------------------------
#define PITCHQ  144
#define AQ_B    (128 * PITCHQ)        // 18432 per Q array
#define KT_B    (64 * PITCHQ)         // 9216 per K array (64 t-rows x 64 d)
#define VT_B    (64 * PITCHQ)         // 9216 V^T (64 d-rows x 64 t)
#define ASTG_B  (2 * KT_B + VT_B)     // 27648
#define ATTN_SMEM (2 * AQ_B + 2 * ASTG_B)   // 92160

__global__ __launch_bounds__(256, 2) void attn_mma_kernel(float* __restrict__ out)
{
    extern __shared__ char smem[];
    const int tid  = threadIdx.x;
    const int w    = tid >> 5, lane = tid & 31;
    const int qi   = (int)gridDim.x - 1 - (int)blockIdx.x;   // long CTAs first
    const int bh   = blockIdx.y;
    const int q0   = qi * 128;
    const int n_kv = 2 * (qi + 1);

    const uint32_t sb  = smem_u32(smem);
    const uint32_t sQh = sb, sQl = sb + AQ_B;
    const uint32_t sT0 = sb + 2 * AQ_B;

    const int gid = lane >> 2, tig = lane & 3;
    const int arow = (lane & 7) + ((lane >> 3) & 1) * 8;
    const uint32_t akb = ((lane >> 4) & 1) * 16;
    const int brow = (lane & 7) + ((lane >> 4) & 1) * 8;
    const uint32_t bkb = ((lane >> 3) & 1) * 16;

    // Q: 128 rows x 64 fp16 (hi+lo) — joins commit group 0
#pragma unroll
    for (int j = 0; j < 4; j++) {
        int idx = tid + 256 * j;
        int row = idx >> 3, seg = idx & 7;
        uint32_t so = (uint32_t)(row * PITCHQ + seg * 16);
        size_t g = ((size_t)bh * Tt + q0 + row) * HD + seg * 8;
        cpa16(sQh + so, g_Qh + g);
        cpa16(sQl + so, g_Ql + g);
    }
    auto loadKV = [&](int kt) {
        const uint32_t base = sT0 + (kt & 1) * ASTG_B;
        const int k0 = kt * 64;
#pragma unroll
        for (int j = 0; j < 2; j++) {
            int idx = tid + 256 * j;
            int row = idx >> 3, seg = idx & 7;
            uint32_t so = (uint32_t)(row * PITCHQ + seg * 16);
            size_t gk = ((size_t)bh * Tt + k0 + row) * HD + seg * 8;
            size_t gv = ((size_t)bh * HD + row) * Tt + k0 + seg * 8;
            cpa16(base + so,            g_Kh + gk);
            cpa16(base + KT_B + so,     g_Kl + gk);
            cpa16(base + 2 * KT_B + so, g_Vt + gv);
        }
        CP_COMMIT();
    };

    loadKV(0);
    if (n_kv > 1) loadKV(1);

    float m0r = -1e30f, m1r = -1e30f, l0r = 0.f, l1r = 0.f;
    float accO[8][4];
#pragma unroll
    for (int na = 0; na < 8; na++)
#pragma unroll
        for (int j = 0; j < 4; j++) accO[na][j] = 0.f;

    for (int kt = 0; kt < n_kv; kt++) {
        if (kt + 1 < n_kv) { CP_WAIT(1); } else { CP_WAIT(0); }
        __syncthreads();

        // Last diagonal tile covers k in [q0+64, q0+128): fully masked for
        // warps 0-3 (q rows q0..q0+63). Skipping their compute is an identity
        // (P rows all zero; m/l/accO unchanged).
        const bool active = !((kt == n_kv - 1) && (w < 4));

        if (active) {
            const uint32_t base = sT0 + (kt & 1) * ASTG_B;
            const int k0 = kt * 64;

            // ---- S = Q K^T (128x64): main fp32, corrections fp16 ----
            float s[8][4];
            uint32_t sc[8][2];
#pragma unroll
            for (int na = 0; na < 8; na++) {
#pragma unroll
                for (int j = 0; j < 4; j++) s[na][j] = 0.f;
                sc[na][0] = 0u; sc[na][1] = 0u;
            }

#pragma unroll
            for (int ks = 0; ks < 4; ks++) {
                const uint32_t qo = (uint32_t)((w * 16 + arow) * PITCHQ) + ks * 32 + akb;
                uint32_t qh[4], ql[4];
                ldsm_x4(qh[0], qh[1], qh[2], qh[3], sQh + qo);
                ldsm_x4(ql[0], ql[1], ql[2], ql[3], sQl + qo);
#pragma unroll
                for (int pb = 0; pb < 4; pb++) {
                    uint32_t kh[4], kl[4];
                    uint32_t bo = (uint32_t)((pb * 16 + brow) * PITCHQ) + ks * 32 + bkb;
                    ldsm_x4(kh[0], kh[1], kh[2], kh[3], base + bo);
                    ldsm_x4(kl[0], kl[1], kl[2], kl[3], base + KT_B + bo);
#pragma unroll
                    for (int n2 = 0; n2 < 2; n2++) {
                        const int na = pb * 2 + n2;
                        mma_ff32(s[na],  qh, kh[n2 * 2], kh[n2 * 2 + 1]);
                        mma_ff16(sc[na], ql, kh[n2 * 2], kh[n2 * 2 + 1]);
                        mma_ff16(sc[na], qh, kl[n2 * 2], kl[n2 * 2 + 1]);
                    }
                }
            }
            // merge corrections
#pragma unroll
            for (int na = 0; na < 8; na++) {
                s[na][0] += h2lo(sc[na][0]);
                s[na][1] += h2hi(sc[na][0]);
                s[na][2] += h2lo(sc[na][1]);
                s[na][3] += h2hi(sc[na][1]);
            }

            // ---- causal mask ----
            const int r0 = q0 + w * 16 + gid, r1 = r0 + 8;
            if (k0 + 63 > r0) {
#pragma unroll
                for (int na = 0; na < 8; na++) {
                    int c0 = k0 + na * 8 + tig * 2, c1 = c0 + 1;
                    if (c0 > r0) s[na][0] = -1e30f;
                    if (c1 > r0) s[na][1] = -1e30f;
                    if (c0 > r1) s[na][2] = -1e30f;
                    if (c1 > r1) s[na][3] = -1e30f;
                }
            }

            // ---- online softmax (base 2, MUFU ex2) ----
            float mx0 = -1e30f, mx1 = -1e30f;
#pragma unroll
            for (int na = 0; na < 8; na++) {
                mx0 = fmaxf(mx0, fmaxf(s[na][0], s[na][1]));
                mx1 = fmaxf(mx1, fmaxf(s[na][2], s[na][3]));
            }
            mx0 = fmaxf(mx0, __shfl_xor_sync(0xffffffffu, mx0, 1));
            mx0 = fmaxf(mx0, __shfl_xor_sync(0xffffffffu, mx0, 2));
            mx1 = fmaxf(mx1, __shfl_xor_sync(0xffffffffu, mx1, 1));
            mx1 = fmaxf(mx1, __shfl_xor_sync(0xffffffffu, mx1, 2));
            float mn0 = fmaxf(m0r, mx0), mn1 = fmaxf(m1r, mx1);
            float c0f = ex2f(m0r - mn0), c1f = ex2f(m1r - mn1);
            m0r = mn0; m1r = mn1;

            float rs0 = 0.f, rs1 = 0.f;
            uint32_t pa[8], pb2[8];       // P fp16 packs: rows gid / gid+8
#pragma unroll
            for (int na = 0; na < 8; na++) {
                float p0 = ex2f(s[na][0] - mn0);
                float p1 = ex2f(s[na][1] - mn0);
                float p2 = ex2f(s[na][2] - mn1);
                float p3 = ex2f(s[na][3] - mn1);
                rs0 += p0 + p1; rs1 += p2 + p3;
                pa[na]  = packh2(p0, p1);
                pb2[na] = packh2(p2, p3);
            }
            rs0 += __shfl_xor_sync(0xffffffffu, rs0, 1);
            rs0 += __shfl_xor_sync(0xffffffffu, rs0, 2);
            rs1 += __shfl_xor_sync(0xffffffffu, rs1, 1);
            rs1 += __shfl_xor_sync(0xffffffffu, rs1, 2);
            l0r = l0r * c0f + rs0;
            l1r = l1r * c1f + rs1;
#pragma unroll
            for (int na = 0; na < 8; na++) {
                accO[na][0] *= c0f; accO[na][1] *= c0f;
                accO[na][2] *= c1f; accO[na][3] *= c1f;
            }

            // ---- O += P V  (single product, P & V fp16; K-dim = 64) ----
            const uint32_t vb = base + 2 * KT_B;
#pragma unroll
            for (int ks = 0; ks < 4; ks++) {
                uint32_t a_p[4] = {pa[2 * ks], pb2[2 * ks], pa[2 * ks + 1], pb2[2 * ks + 1]};
#pragma unroll
                for (int pb = 0; pb < 4; pb++) {
                    uint32_t vh[4];
                    uint32_t bo = (uint32_t)((pb * 16 + brow) * PITCHQ) + ks * 32 + bkb;
                    ldsm_x4(vh[0], vh[1], vh[2], vh[3], vb + bo);
#pragma unroll
                    for (int n2 = 0; n2 < 2; n2++)
                        mma_ff32(accO[pb * 2 + n2], a_p, vh[n2 * 2], vh[n2 * 2 + 1]);
                }
            }
        }

        if (kt + 2 < n_kv) {
            __syncthreads();      // buffer (kt&1) free across all warps
            loadKV(kt + 2);
        }
    }

    // ---- epilogue ----
    const int b = bh >> 4, hh = bh & 15;
    const float inv0 = 1.0f / l0r, inv1 = 1.0f / l1r;
    const int r0 = q0 + w * 16 + gid, r1 = r0 + 8;
#pragma unroll
    for (int na = 0; na < 8; na++) {
        const int col = hh * 64 + na * 8 + tig * 2;
        float2 o0 = make_float2(accO[na][0] * inv0, accO[na][1] * inv0);
        float2 o1 = make_float2(accO[na][2] * inv1, accO[na][3] * inv1);
        *(float2*)&out[((size_t)(b * Tt + r0)) * Dm + col] = o0;
        *(float2*)&out[((size_t)(b * Tt + r1)) * Dm + col] = o1;
    }
}

// ---------------------------------------------------------------------------
extern "C" void kernel_launch(void* const* d_in, const int* in_sizes, int n_in,
                              void* d_out, int out_size)
{
    (void)in_sizes; (void)n_in; (void)out_size;
    const float* x  = (const float*)d_in[0];
    const float* Wq = (const float*)d_in[1];
    const float* bq = (const float*)d_in[2];
    const float* Wk = (const float*)d_in[3];
    const float* bk = (const float*)d_in[4];
    const float* Wv = (const float*)d_in[5];
    const float* bv = (const float*)d_in[6];
    float* out = (float*)d_out;

    const int nblk = (NX4 + 3 * NW4) / 512;     // 5632
    split_all<<<nblk, 256>>>(x, Wq, Wk, Wv);

    cudaFuncSetAttribute(proj_mma_kernel,
                         cudaFuncAttributeMaxDynamicSharedMemorySize, GEMM_SMEM);
    dim3 pg(Mtot / 128, Dm / 128, 2);           // Q and K
    proj_mma_kernel<<<pg, 256, GEMM_SMEM>>>(bq, bk);

    cudaFuncSetAttribute(proj_v_kernel,
                         cudaFuncAttributeMaxDynamicSharedMemorySize, GEMM_V_SMEM);
    proj_v_kernel<<<dim3(Mtot / 128, Dm / 128), 256, GEMM_V_SMEM>>>(bv);

    cudaFuncSetAttribute(attn_mma_kernel,
                         cudaFuncAttributeMaxDynamicSharedMemorySize, ATTN_SMEM);
    attn_mma_kernel<<<dim3(16, 64), 256, ATTN_SMEM>>>(out);
}